// round 12
// baseline (speedup 1.0000x reference)
#include <cuda_runtime.h>
#include <cstdint>

// DTree_84061099917446 — soft decision tree forward pass.
// N=262144 rows, F=32, depth 8, 255 nodes, 256 leaves, C=1.
//
// R12: kill the dominant L1 traffic (B-fragment LDS.128 = 62% of per-tile
// wavefronts in R11). Producers now each own 32 columns x all 64 rows:
// their B slice (bf16 hi/lo fragments) fits in 32 registers, loaded from
// GMEM ONCE per kernel. GEMM switched to mma.sync.m16n8k16.bf16 with 4-pass
// hi/lo split (8 MMA per 8-col group vs tf32's 12). A loads are direct
// LDG.64 feature-pairs split in-loop (PRMT + CVT). z double-buffered in
// smem (stride 257, conflict-free); consumers (8 warps) walk the tree as in
// R11 (4 threads/row, literal node ids, register stack).

#define F_        32
#define NODES_    255
#define N_ROWS    262144
#define ROWS_T    64
#define NTILES    (N_ROWS / ROWS_T)     // 4096
#define TPB       512
#define GRID_     148
#define LOG2E_F   1.4426950408889634f

typedef unsigned int u32;

// ---- smem layout (byte offsets) ----
#define ZSTR      257                    // floats; odd -> conflict-free
#define SM_Z0     0                      // 64*257*4 = 65792
#define SM_Z1     65792
#define SM_PR     131584                 // 128 float2
#define SM_PBUF   132608                 // 256 floats
#define SM_TOTAL  133632

// Prologue outputs (scratch via __device__ globals — no allocation).
// B fragments, mma order: [n>>3][lane] -> float4 = u32{s0r0,s0r1,s1r0,s1r1}
__device__ __align__(16) float4 g_Bh4[1024];   // bf16x2 hi pairs
__device__ __align__(16) float4 g_Bl4[1024];   // bf16x2 lo pairs
__device__ float  g_bias[256];                 // +log2e*c (idx 255: 0)
__device__ float2 g_pr[128];                   // (clsR, clsL - clsR)

// ---------------------------------------------------------------------------
// Prologue: one block, 256 threads; thread t = node t (255 = zero pad).
// Packs W' = -log2e*relu(fi) as bf16 hi (truncated top-16) + bf16 lo
// (residual, round-nearest) in m16n8k16 B-fragment order.
// ---------------------------------------------------------------------------
__global__ void prep_kernel(const float* __restrict__ fi,
                            const float* __restrict__ fs,
                            const float* __restrict__ cls) {
    int t = threadIdx.x;
    if (t < 256) {
        float wp[F_];
        float bias = 0.0f;
        #pragma unroll
        for (int f = 0; f < F_; ++f) {
            float v = 0.0f;
            if (t < NODES_) {
                int idx = t * F_ + f;
                float w = fmaxf(fi[idx], 0.0f);
                float s = 1.0f / (1.0f + expf(-fs[idx]));
                bias += w * s;
                v = -LOG2E_F * w;
            }
            wp[f] = v;
        }
        int cidx = t >> 3, gcol = t & 7;
        #pragma unroll
        for (int tig = 0; tig < 4; ++tig) {
            u32 qh[4], ql[4];
            #pragma unroll
            for (int s = 0; s < 2; ++s)
                #pragma unroll
                for (int r = 0; r < 2; ++r) {
                    int k = 16 * s + 8 * r + 2 * tig;
                    u32 bx = __float_as_uint(wp[k]);
                    u32 by = __float_as_uint(wp[k + 1]);
                    // hi = {lo16: top16(x), hi16: top16(y)} (truncated bf16)
                    u32 hi = __byte_perm(bx, by, 0x7632);
                    float lx = wp[k]     - __uint_as_float(bx & 0xFFFF0000u);
                    float ly = wp[k + 1] - __uint_as_float(by & 0xFFFF0000u);
                    u32 lo;
                    asm("cvt.rn.bf16x2.f32 %0, %1, %2;"
                        : "=r"(lo) : "f"(ly), "f"(lx));
                    qh[s * 2 + r] = hi;
                    ql[s * 2 + r] = lo;
                }
            int base = cidx * 32 + gcol * 4 + tig;
            g_Bh4[base] = make_float4(__uint_as_float(qh[0]), __uint_as_float(qh[1]),
                                      __uint_as_float(qh[2]), __uint_as_float(qh[3]));
            g_Bl4[base] = make_float4(__uint_as_float(ql[0]), __uint_as_float(ql[1]),
                                      __uint_as_float(ql[2]), __uint_as_float(ql[3]));
        }
        g_bias[t] = (t < NODES_) ? (LOG2E_F * bias) : 0.0f;
    }
    if (t < 128) {
        float lv = cls[2 * t];
        float rv = cls[2 * t + 1];
        g_pr[t] = make_float2(rv, lv - rv);
    }
}

// ---------------------------------------------------------------------------
__device__ __forceinline__ void mma16(float (&d)[4], const u32* a,
                                      u32 b0, u32 b1) {
    asm volatile(
        "mma.sync.aligned.m16n8k16.row.col.f32.bf16.bf16.f32 "
        "{%0,%1,%2,%3}, {%4,%5,%6,%7}, {%8,%9}, {%0,%1,%2,%3};"
        : "+f"(d[0]), "+f"(d[1]), "+f"(d[2]), "+f"(d[3])
        : "r"(a[0]), "r"(a[1]), "r"(a[2]), "r"(a[3]), "r"(b0), "r"(b1));
}

__device__ __forceinline__ float fgate(float y) {   // 1 / (1 + 2^y)
    float e, g;
    asm("ex2.approx.f32 %0, %1;" : "=f"(e) : "f"(y));
    float d = 1.0f + e;
    asm("rcp.approx.f32 %0, %1;" : "=f"(g) : "f"(d));
    return g;
}

// split float2 -> bf16x2 hi (truncate) + bf16x2 lo (residual, rn)
__device__ __forceinline__ void split2(float2 v, u32& hi, u32& lo) {
    u32 bx = __float_as_uint(v.x), by = __float_as_uint(v.y);
    hi = __byte_perm(bx, by, 0x7632);
    float lx = v.x - __uint_as_float(bx & 0xFFFF0000u);
    float ly = v.y - __uint_as_float(by & 0xFFFF0000u);
    asm("cvt.rn.bf16x2.f32 %0, %1, %2;" : "=r"(lo) : "f"(ly), "f"(lx));
}

#define CTA_BAR()  asm volatile("barrier.sync 0;" ::: "memory")
#define EPI_BAR()  asm volatile("barrier.sync 1, 256;" ::: "memory")

// ---------------------------------------------------------------------------
// Register-stack walk of the subtree rooted at NODE (literal), depths 2..7.
// ---------------------------------------------------------------------------
template<int DEPTH, int NODE>
__device__ __forceinline__ void walk(const float*  __restrict__ zr,
                                     const float2* __restrict__ spr,
                                     float prod, float& acc) {
    float g = fgate(zr[NODE]);
    if constexpr (DEPTH == 7) {
        float2 pr = spr[NODE - 127];
        acc = fmaf(prod, fmaf(g, pr.y, pr.x), acc);
    } else {
        float r = fmaf(-prod, g, prod);
        walk<DEPTH + 1, 2 * NODE + 1>(zr, spr, prod * g, acc);
        walk<DEPTH + 1, 2 * NODE + 2>(zr, spr, r, acc);
    }
}

// ---------------------------------------------------------------------------
__global__ void __launch_bounds__(TPB, 1)
dtree_kernel(const float* __restrict__ x,
             float* __restrict__ out) {
    extern __shared__ __align__(16) char smem[];
    float2* spr  = reinterpret_cast<float2*>(smem + SM_PR);
    float*  pbuf = reinterpret_cast<float*>(smem + SM_PBUF);

    int tid  = threadIdx.x;
    int lane = tid & 31;
    int wrp  = tid >> 5;
    int bid  = blockIdx.x;
    int nblk = (NTILES - bid + GRID_ - 1) / GRID_;

    if (tid < 128) spr[tid] = g_pr[tid];   // visible after first CTA_BAR

    if (wrp < 8) {
        // ============ producers: bf16 4-pass GEMM, B resident in regs ======
        int gid = lane >> 2, tig = lane & 3;

        u32 bh[16], bl[16];                 // [nt*4 + s*2 + r]
        float2 bias2[4];
        #pragma unroll
        for (int nt = 0; nt < 4; ++nt) {
            float4 h = __ldg(&g_Bh4[(wrp * 4 + nt) * 32 + lane]);
            float4 l = __ldg(&g_Bl4[(wrp * 4 + nt) * 32 + lane]);
            bh[nt * 4]     = __float_as_uint(h.x);
            bh[nt * 4 + 1] = __float_as_uint(h.y);
            bh[nt * 4 + 2] = __float_as_uint(h.z);
            bh[nt * 4 + 3] = __float_as_uint(h.w);
            bl[nt * 4]     = __float_as_uint(l.x);
            bl[nt * 4 + 1] = __float_as_uint(l.y);
            bl[nt * 4 + 2] = __float_as_uint(l.z);
            bl[nt * 4 + 3] = __float_as_uint(l.w);
            bias2[nt] = *reinterpret_cast<const float2*>(
                g_bias + wrp * 32 + nt * 8 + 2 * tig);
        }

        for (int step = 0; step <= nblk; ++step) {
            CTA_BAR();
            if (step >= nblk) continue;
            int tile = bid + step * GRID_;
            float* sz = reinterpret_cast<float*>(
                smem + ((step & 1) ? SM_Z1 : SM_Z0));
            const float2* xt2 = reinterpret_cast<const float2*>(
                x + (size_t)tile * ROWS_T * F_);

            #pragma unroll
            for (int m = 0; m < 4; ++m) {
                int r0 = m * 16 + gid;
                // A fragments: rows {r0, r0+8}, k pairs {2t, 8+2t} (+16s)
                u32 ah[8], al[8];
                #pragma unroll
                for (int s = 0; s < 2; ++s)
                    #pragma unroll
                    for (int p = 0; p < 2; ++p) {
                        int kk = (16 * s + 8 * p + 2 * tig) >> 1;
                        float2 v0 = __ldg(&xt2[r0 * 16 + kk]);
                        float2 v1 = __ldg(&xt2[(r0 + 8) * 16 + kk]);
                        int ix = s * 4 + p * 2;
                        split2(v0, ah[ix],     al[ix]);
                        split2(v1, ah[ix + 1], al[ix + 1]);
                    }
                #pragma unroll
                for (int nt = 0; nt < 4; ++nt) {
                    float d[4]  = {bias2[nt].x, bias2[nt].y,
                                   bias2[nt].x, bias2[nt].y};
                    float e[4]  = {0.f, 0.f, 0.f, 0.f};
                    float f4[4] = {0.f, 0.f, 0.f, 0.f};
                    #pragma unroll
                    for (int s = 0; s < 2; ++s) {
                        u32 b0h = bh[nt * 4 + s * 2], b1h = bh[nt * 4 + s * 2 + 1];
                        u32 b0l = bl[nt * 4 + s * 2], b1l = bl[nt * 4 + s * 2 + 1];
                        mma16(d,  &ah[s * 4], b0h, b1h);   // hi*hi (+bias)
                        mma16(e,  &ah[s * 4], b0l, b1l);   // hi*lo
                        mma16(e,  &al[s * 4], b0h, b1h);   // lo*hi
                        mma16(f4, &al[s * 4], b0l, b1l);   // lo*lo
                    }
                    int c0 = wrp * 32 + nt * 8 + 2 * tig;
                    float* z0 = sz + r0 * ZSTR + c0;
                    float* z1 = sz + (r0 + 8) * ZSTR + c0;
                    z0[0] = d[0] + e[0] + f4[0];
                    z0[1] = d[1] + e[1] + f4[1];
                    z1[0] = d[2] + e[2] + f4[2];
                    z1[1] = d[3] + e[3] + f4[3];
                }
            }
        }
    } else {
        // ============ consumers: tree walk ============
        int etid = tid - 256;
        int row  = etid & 63;
        int j    = etid >> 6;
        for (int step = 0; step <= nblk; ++step) {
            CTA_BAR();
            if (step < 1) continue;
            int tile = bid + (step - 1) * GRID_;
            const float* sz = reinterpret_cast<const float*>(
                smem + (((step - 1) & 1) ? SM_Z1 : SM_Z0));
            const float* zr = sz + row * ZSTR;

            float g0 = fgate(zr[0]);
            float ga = fgate(zr[1 + (j >> 1)]);
            float p1 = (j & 2) ? (1.0f - g0) : g0;
            float p2 = (j & 1) ? (1.0f - ga) : ga;
            float prod = p1 * p2;
            float acc = 0.0f;
            switch (j) {
                case 0:  walk<2, 3>(zr, spr, prod, acc); break;
                case 1:  walk<2, 4>(zr, spr, prod, acc); break;
                case 2:  walk<2, 5>(zr, spr, prod, acc); break;
                default: walk<2, 6>(zr, spr, prod, acc); break;
            }
            pbuf[etid] = acc;
            EPI_BAR();
            if (j == 0) {
                float s = (pbuf[row] + pbuf[row + 64]) +
                          (pbuf[row + 128] + pbuf[row + 192]);
                out[tile * ROWS_T + row] = s;
            }
        }
    }
}

// ---------------------------------------------------------------------------
extern "C" void kernel_launch(void* const* d_in, const int* in_sizes, int n_in,
                              void* d_out, int out_size) {
    const float* x   = (const float*)d_in[0];   // (N, 32)
    const float* fi  = (const float*)d_in[1];   // (255*32, 1)
    const float* fs  = (const float*)d_in[2];   // (255*32, 1)
    const float* cls = (const float*)d_in[3];   // (256, 1)
    float* out = (float*)d_out;                 // (N, 1) float32

    cudaFuncSetAttribute(dtree_kernel,
                         cudaFuncAttributeMaxDynamicSharedMemorySize, SM_TOTAL);
    prep_kernel<<<1, 256>>>(fi, fs, cls);
    dtree_kernel<<<GRID_, TPB, SM_TOTAL>>>(x, out);
}